// round 3
// baseline (speedup 1.0000x reference)
#include <cuda_runtime.h>
#include <cstdint>

// Problem dims
#define BB 2
#define TT 2048
#define CC 1024
#define HH 16
#define DD 64
#define FF 4096
#define WW 256
#define LL 2
#define NTOK (BB*TT)   // 4096

// ---------------- scratch (static device globals; no runtime allocation) ----
__device__ float g_h   [NTOK*CC];     // 16 MB  rmsnorm output
__device__ float g_qkv [NTOK*3*CC];   // 48 MB
__device__ float g_att [NTOK*CC];     // 16 MB  attention output (pre-proj)
__device__ float g_proj[NTOK*CC];     // 16 MB  attn_out (post-proj)
__device__ float g_big [NTOK*FF];     // 64 MB  ffn gate/up/t
__device__ float g_ret [BB*CC];
__device__ float g_gates[NTOK*2];     // (g0, g2) per token

// ---------------- RMSNorm ----------------
__global__ __launch_bounds__(256) void rmsnorm_k(const float* __restrict__ x,
                                                 const float* __restrict__ g,
                                                 float* __restrict__ out) {
    int t = blockIdx.x;
    const float* xr = x + (size_t)t * CC;
    float ss = 0.f;
    for (int c = threadIdx.x; c < CC; c += 256) { float v = xr[c]; ss += v * v; }
    __shared__ float red[256];
    red[threadIdx.x] = ss; __syncthreads();
    for (int o = 128; o > 0; o >>= 1) {
        if (threadIdx.x < o) red[threadIdx.x] += red[threadIdx.x + o];
        __syncthreads();
    }
    float r = rsqrtf(red[0] * (1.0f / CC) + 1e-6f);
    float* orow = out + (size_t)t * CC;
    for (int c = threadIdx.x; c < CC; c += 256) orow[c] = xr[c] * r * g[c];
}

// ---------------- SGEMM: C[M,N] = A[M,K] @ B[K,N], row-major, fp32 ----------
// EPI: 0 store; 1 silu(acc); 2 C=acc*C (elementwise mul with existing C);
//      3 C=acc+C (residual add)
template <int EPI>
__global__ __launch_bounds__(256) void sgemm_k(const float* __restrict__ A,
                                               const float* __restrict__ Bm,
                                               float* __restrict__ C,
                                               int M, int N, int K) {
    __shared__ float As[8][128];
    __shared__ float Bs[8][128];
    int tid = threadIdx.x;
    int m0 = blockIdx.y * 128, n0 = blockIdx.x * 128;

    int arow = tid >> 1, acol = (tid & 1) * 4;   // A: 128 rows x 8 cols
    int brow = tid >> 5, bcol = (tid & 31) * 4;  // B: 8 rows x 128 cols
    const float* Aptr = A + (size_t)(m0 + arow) * K + acol;
    const float* Bptr = Bm + (size_t)brow * N + n0 + bcol;

    int tx = tid & 15, ty = tid >> 4;            // 16x16 thread grid, 8x8 each
    float acc[8][8];
    #pragma unroll
    for (int i = 0; i < 8; i++)
        #pragma unroll
        for (int j = 0; j < 8; j++) acc[i][j] = 0.f;

    for (int k0 = 0; k0 < K; k0 += 8) {
        float4 av = *(const float4*)(Aptr + k0);
        float4 bv = *(const float4*)(Bptr + (size_t)k0 * N);
        As[acol + 0][arow] = av.x;
        As[acol + 1][arow] = av.y;
        As[acol + 2][arow] = av.z;
        As[acol + 3][arow] = av.w;
        *(float4*)&Bs[brow][bcol] = bv;
        __syncthreads();
        #pragma unroll
        for (int kk = 0; kk < 8; kk++) {
            float a[8], b[8];
            #pragma unroll
            for (int i = 0; i < 8; i++) a[i] = As[kk][ty * 8 + i];
            #pragma unroll
            for (int j = 0; j < 8; j++) b[j] = Bs[kk][tx * 8 + j];
            #pragma unroll
            for (int i = 0; i < 8; i++)
                #pragma unroll
                for (int j = 0; j < 8; j++) acc[i][j] += a[i] * b[j];
        }
        __syncthreads();
    }

    #pragma unroll
    for (int i = 0; i < 8; i++) {
        float* Cp = C + (size_t)(m0 + ty * 8 + i) * N + n0 + tx * 8;
        #pragma unroll
        for (int j = 0; j < 8; j++) {
            float v = acc[i][j];
            if (EPI == 0)      Cp[j] = v;
            else if (EPI == 1) Cp[j] = v / (1.f + __expf(-v));   // silu
            else if (EPI == 2) Cp[j] = v * Cp[j];
            else               Cp[j] = v + Cp[j];
        }
    }
}

// ---------------- sliding-window attention --------------------------------
// grid (T/64, H, B), 256 threads. 64-query tile, 32-key tiles, online softmax.
__global__ __launch_bounds__(256) void attn_k(const float* __restrict__ qkv,
                                              float* __restrict__ out) {
    __shared__ float Qs[64][65];
    __shared__ float Ks[32][65];
    __shared__ float Vs[32][65];
    __shared__ float Ps[64][33];

    int qt = blockIdx.x, h = blockIdx.y, b = blockIdx.z;
    int tid = threadIdx.x;
    int qbase = qt * 64;
    int tokbase = b * TT + qbase;

    // load Q tile
    for (int i = tid; i < 64 * 64; i += 256) {
        int r = i >> 6, c = i & 63;
        Qs[r][c] = qkv[(size_t)(tokbase + r) * 3072 + h * 64 + c];
    }

    int ty = tid >> 2, tx = tid & 3;   // ty: query 0..63, tx: 4-way split
    float O[16];
    #pragma unroll
    for (int j = 0; j < 16; j++) O[j] = 0.f;
    float m = -1e30f, l = 0.f;

    int kt0 = (qbase - (WW - 1)) > 0 ? (qbase - (WW - 1)) >> 5 : 0;
    int kt1 = 2 * qt + 1;
    int q_g = qbase + ty;

    __syncthreads();
    for (int kt = kt0; kt <= kt1; kt++) {
        int kb = kt * 32;
        for (int i = tid; i < 32 * 64; i += 256) {
            int r = i >> 6, c = i & 63;
            size_t base = (size_t)(b * TT + kb + r) * 3072 + h * 64 + c;
            Ks[r][c] = qkv[base + 1024];
            Vs[r][c] = qkv[base + 2048];
        }
        __syncthreads();

        // scores for 8 keys per thread
        float s[8];
        #pragma unroll
        for (int i = 0; i < 8; i++) s[i] = 0.f;
        for (int d = 0; d < 64; d++) {
            float qv = Qs[ty][d];
            #pragma unroll
            for (int i = 0; i < 8; i++) s[i] += qv * Ks[tx * 8 + i][d];
        }
        float mx = -1e30f;
        #pragma unroll
        for (int i = 0; i < 8; i++) {
            int k_g = kb + tx * 8 + i;
            bool ok = (k_g <= q_g) && (k_g >= q_g - (WW - 1));
            s[i] = ok ? s[i] * 0.125f : -__int_as_float(0x7f800000); // -inf
            mx = fmaxf(mx, s[i]);
        }
        mx = fmaxf(mx, __shfl_xor_sync(0xffffffffu, mx, 1));
        mx = fmaxf(mx, __shfl_xor_sync(0xffffffffu, mx, 2));
        float mn = fmaxf(m, mx);
        float alpha = __expf(m - mn);
        m = mn;
        float ls = 0.f;
        #pragma unroll
        for (int i = 0; i < 8; i++) {
            float p = __expf(s[i] - mn);
            Ps[ty][tx * 8 + i] = p;
            ls += p;
        }
        ls += __shfl_xor_sync(0xffffffffu, ls, 1);
        ls += __shfl_xor_sync(0xffffffffu, ls, 2);
        l = l * alpha + ls;
        #pragma unroll
        for (int j = 0; j < 16; j++) O[j] *= alpha;
        __syncwarp();
        for (int kk = 0; kk < 32; kk++) {
            float p = Ps[ty][kk];
            #pragma unroll
            for (int j = 0; j < 16; j++) O[j] += p * Vs[kk][tx * 16 + j];
        }
        __syncthreads();
    }
    float inv = 1.f / l;
    float* orow = out + (size_t)(tokbase + ty) * 1024 + h * 64 + tx * 16;
    #pragma unroll
    for (int j = 0; j < 16; j++) orow[j] = O[j] * inv;
}

// ---------------- gate: softmax([h@gw0, -1e9, h@gw2]) ----------------------
__global__ __launch_bounds__(128) void gate_k(const float* __restrict__ h,
                                              const float* __restrict__ gw,
                                              const float* __restrict__ gb,
                                              float* __restrict__ gates) {
    int t = blockIdx.x;
    const float* hr = h + (size_t)t * CC;
    float s0 = 0.f, s2 = 0.f;
    for (int c = threadIdx.x; c < CC; c += 128) {
        float hv = hr[c];
        s0 += hv * gw[c * 3 + 0];
        s2 += hv * gw[c * 3 + 2];
    }
    __shared__ float r0[128], r2[128];
    r0[threadIdx.x] = s0; r2[threadIdx.x] = s2; __syncthreads();
    for (int o = 64; o > 0; o >>= 1) {
        if (threadIdx.x < o) { r0[threadIdx.x] += r0[threadIdx.x + o];
                               r2[threadIdx.x] += r2[threadIdx.x + o]; }
        __syncthreads();
    }
    if (threadIdx.x == 0) {
        float l0 = r0[0] + gb[0], l2 = r2[0] + gb[2];
        float mx = fmaxf(l0, l2);
        float e0 = __expf(l0 - mx), e2 = __expf(l2 - mx);
        float inv = 1.f / (e0 + e2);   // exp(-1e9 - mx) underflows to 0, as in ref
        gates[t * 2 + 0] = e0 * inv;
        gates[t * 2 + 1] = e2 * inv;
    }
}

// ---------------- retrieval projection: (B,C) @ (C,C) ----------------------
__global__ __launch_bounds__(128) void ret_k(const float* __restrict__ rc,
                                             const float* __restrict__ W,
                                             float* __restrict__ out) {
    int b = blockIdx.y;
    int c = blockIdx.x * 128 + threadIdx.x;
    float acc = 0.f;
    const float* r = rc + (size_t)b * CC;
    for (int k = 0; k < CC; k++) acc += r[k] * W[(size_t)k * CC + c];
    out[(size_t)b * CC + c] = acc;
}

// ---------------- gated mix + residual -------------------------------------
__global__ __launch_bounds__(256) void mix_k(float* __restrict__ x,
                                             const float* __restrict__ ao,
                                             const float* __restrict__ ret,
                                             const float* __restrict__ gates) {
    int idx = blockIdx.x * 256 + threadIdx.x;
    int t = idx >> 10, c = idx & 1023, b = t >> 11;
    x[idx] += gates[t * 2] * ao[idx] + gates[t * 2 + 1] * ret[b * CC + c];
}

// ---------------- launch ----------------------------------------------------
extern "C" void kernel_launch(void* const* d_in, const int* in_sizes, int n_in,
                              void* d_out, int out_size) {
    const float* x_in   = (const float*)d_in[0];
    const float* retc   = (const float*)d_in[1];
    const float* norm1g = (const float*)d_in[2];
    const float* Wqkv   = (const float*)d_in[3];
    const float* Wproj  = (const float*)d_in[4];
    const float* gateW  = (const float*)d_in[5];
    const float* gateB  = (const float*)d_in[6];
    const float* retW   = (const float*)d_in[7];
    const float* norm2g = (const float*)d_in[8];
    const float* WfG    = (const float*)d_in[9];
    const float* WfU    = (const float*)d_in[10];
    const float* WfD    = (const float*)d_in[11];
    float* x = (float*)d_out;

    float *hb, *qkvb, *attb, *projb, *bigb, *retb, *gatesb;
    cudaGetSymbolAddress((void**)&hb,    g_h);
    cudaGetSymbolAddress((void**)&qkvb,  g_qkv);
    cudaGetSymbolAddress((void**)&attb,  g_att);
    cudaGetSymbolAddress((void**)&projb, g_proj);
    cudaGetSymbolAddress((void**)&bigb,  g_big);
    cudaGetSymbolAddress((void**)&retb,  g_ret);
    cudaGetSymbolAddress((void**)&gatesb,g_gates);

    cudaMemcpyAsync(x, x_in, sizeof(float) * (size_t)NTOK * CC,
                    cudaMemcpyDeviceToDevice, 0);

    for (int l = 0; l < LL; l++) {
        const float* Wqkv_l = Wqkv + (size_t)l * CC * 3 * CC;
        const float* Wproj_l = Wproj + (size_t)l * CC * CC;
        const float* gateW_l = gateW + (size_t)l * CC * 3;
        const float* gateB_l = gateB + (size_t)l * 3;
        const float* retW_l  = retW  + (size_t)l * CC * CC;
        const float* WfG_l = WfG + (size_t)l * CC * FF;
        const float* WfU_l = WfU + (size_t)l * CC * FF;
        const float* WfD_l = WfD + (size_t)l * FF * CC;

        rmsnorm_k<<<NTOK, 256>>>(x, norm1g + l * CC, hb);
        sgemm_k<0><<<dim3(3 * CC / 128, NTOK / 128), 256>>>(hb, Wqkv_l, qkvb,
                                                            NTOK, 3 * CC, CC);
        attn_k<<<dim3(TT / 64, HH, BB), 256>>>(qkvb, attb);
        sgemm_k<0><<<dim3(CC / 128, NTOK / 128), 256>>>(attb, Wproj_l, projb,
                                                        NTOK, CC, CC);
        gate_k<<<NTOK, 128>>>(hb, gateW_l, gateB_l, gatesb);
        ret_k<<<dim3(CC / 128, BB), 128>>>(retc, retW_l, retb);
        mix_k<<<NTOK * CC / 256, 256>>>(x, projb, retb, gatesb);

        rmsnorm_k<<<NTOK, 256>>>(x, norm2g + l * CC, hb);
        sgemm_k<1><<<dim3(FF / 128, NTOK / 128), 256>>>(hb, WfG_l, bigb,
                                                        NTOK, FF, CC);
        sgemm_k<2><<<dim3(FF / 128, NTOK / 128), 256>>>(hb, WfU_l, bigb,
                                                        NTOK, FF, CC);
        sgemm_k<3><<<dim3(CC / 128, NTOK / 128), 256>>>(bigb, WfD_l, x,
                                                        NTOK, CC, FF);
    }
}

// round 10
// speedup vs baseline: 2.6788x; 2.6788x over previous
#include <cuda_runtime.h>
#include <cstdint>

// Problem dims
#define BB 2
#define TT 2048
#define CC 1024
#define HH 16
#define DD 64
#define FF 4096
#define WW 256
#define LL 2
#define NTOK (BB*TT)   // 4096

// ---------------- scratch (static device globals; no runtime allocation) ----
__device__ float g_h   [NTOK*CC];
__device__ float g_qkv [NTOK*3*CC];
__device__ float g_att [NTOK*CC];
__device__ float g_proj[NTOK*CC];
__device__ float g_big [NTOK*FF];
__device__ float g_ret [BB*CC];
__device__ float g_gates[NTOK*2];

// ==================== helpers ==============================================
__device__ __forceinline__ uint32_t smem_u32(const void* p) {
    uint32_t a;
    asm("{ .reg .u64 t; cvta.to.shared.u64 t, %1; cvt.u32.u64 %0, t; }"
        : "=r"(a) : "l"(p));
    return a;
}
__device__ __forceinline__ void cpa16(uint32_t s, const void* g) {
    asm volatile("cp.async.ca.shared.global [%0], [%1], 16;"
                 :: "r"(s), "l"(g) : "memory");
}
__device__ __forceinline__ uint32_t cvt_tf32(float f) {
    uint32_t u;
    asm("cvt.rna.tf32.f32 %0, %1;" : "=r"(u) : "f"(f));
    return u;
}
__device__ __forceinline__ void mma_tf32(float* c, const uint32_t* a,
                                         const uint32_t* b) {
    asm volatile(
        "mma.sync.aligned.m16n8k8.row.col.f32.tf32.tf32.f32 "
        "{%0,%1,%2,%3}, {%4,%5,%6,%7}, {%8,%9}, {%0,%1,%2,%3};"
        : "+f"(c[0]), "+f"(c[1]), "+f"(c[2]), "+f"(c[3])
        : "r"(a[0]), "r"(a[1]), "r"(a[2]), "r"(a[3]), "r"(b[0]), "r"(b[1]));
}

// ==================== tf32 mma.sync GEMM ===================================
// C[M,N] = A[M,K] @ B[K,N], row-major fp32, tf32 tensor-core math.
// CTA 128x128, 256 thr (8 warps, 4x2), warp tile 32x64, K stage 32,
// cp.async double buffer. EPI: 0 store; 1 silu; 2 C=acc*C; 3 C=acc+C
#define AS_STRIDE 36
#define BS_STRIDE 136
#define A_ELEMS (128*AS_STRIDE)           // 4608
#define B_ELEMS (32*BS_STRIDE)            // 4352
#define SMEM_BYTES ((A_ELEMS + B_ELEMS) * 2 * 4)   // 71680

template <int EPI>
__global__ __launch_bounds__(256)
void tgemm_k(const float* __restrict__ A, const float* __restrict__ Bm,
             float* __restrict__ C, int M, int N, int K) {
    extern __shared__ float smem[];
    const int aOff[2] = {0, A_ELEMS + B_ELEMS};
    const int bOff[2] = {A_ELEMS, 2 * A_ELEMS + B_ELEMS};
    uint32_t sbase = smem_u32(smem);

    int tid = threadIdx.x;
    int wid = tid >> 5, lane = tid & 31;
    int wm = wid & 3, wn = wid >> 2;
    int g = lane >> 2, tg = lane & 3;
    int m0 = blockIdx.y * 128, n0 = blockIdx.x * 128;
    int S = K >> 5;

    float acc[2][8][4];
    #pragma unroll
    for (int mt = 0; mt < 2; mt++)
        #pragma unroll
        for (int nt = 0; nt < 8; nt++)
            #pragma unroll
            for (int i = 0; i < 4; i++) acc[mt][nt][i] = 0.f;

    // per-thread fill coordinates
    const int arow = tid >> 3, ac4 = tid & 7;   // + it*32 rows
    const int bk = tid >> 5, bn4 = tid & 31;    // + it*8 k-rows

    // -------- stage issue (8 cp.async of 16B per thread) --------
    auto issue = [&](int s, int buf) {
        int k0 = s << 5;
        uint32_t aB = sbase + aOff[buf] * 4;
        uint32_t bB = sbase + bOff[buf] * 4;
        #pragma unroll
        for (int it = 0; it < 4; it++) {
            int row = arow + it * 32;
            cpa16(aB + (row * AS_STRIDE + ac4 * 4) * 4,
                  A + (size_t)(m0 + row) * K + k0 + ac4 * 4);
        }
        #pragma unroll
        for (int it = 0; it < 4; it++) {
            int k = bk + it * 8;
            cpa16(bB + (k * BS_STRIDE + bn4 * 4) * 4,
                  Bm + (size_t)(k0 + k) * N + n0 + bn4 * 4);
        }
        asm volatile("cp.async.commit_group;" ::: "memory");
    };

    issue(0, 0);
    if (S > 1) issue(1, 1);

    for (int s = 0; s < S; s++) {
        if (s < S - 1)
            asm volatile("cp.async.wait_group 1;" ::: "memory");
        else
            asm volatile("cp.async.wait_group 0;" ::: "memory");
        __syncthreads();

        const float* Af = smem + aOff[s & 1];
        const float* Bf = smem + bOff[s & 1];
        #pragma unroll
        for (int ks = 0; ks < 4; ks++) {
            int k8 = ks * 8;
            uint32_t a[2][4];
            #pragma unroll
            for (int mt = 0; mt < 2; mt++) {
                int r0 = wm * 32 + mt * 16 + g;
                a[mt][0] = cvt_tf32(Af[r0 * AS_STRIDE + k8 + tg]);
                a[mt][1] = cvt_tf32(Af[(r0 + 8) * AS_STRIDE + k8 + tg]);
                a[mt][2] = cvt_tf32(Af[r0 * AS_STRIDE + k8 + tg + 4]);
                a[mt][3] = cvt_tf32(Af[(r0 + 8) * AS_STRIDE + k8 + tg + 4]);
            }
            uint32_t b[8][2];
            #pragma unroll
            for (int nt = 0; nt < 8; nt++) {
                int col = wn * 64 + nt * 8 + g;
                b[nt][0] = cvt_tf32(Bf[(k8 + tg) * BS_STRIDE + col]);
                b[nt][1] = cvt_tf32(Bf[(k8 + tg + 4) * BS_STRIDE + col]);
            }
            #pragma unroll
            for (int mt = 0; mt < 2; mt++)
                #pragma unroll
                for (int nt = 0; nt < 8; nt++)
                    mma_tf32(acc[mt][nt], a[mt], b[nt]);
        }
        __syncthreads();
        if (s + 2 < S) issue(s + 2, s & 1);
    }

    // -------- epilogue --------
    #pragma unroll
    for (int mt = 0; mt < 2; mt++) {
        #pragma unroll
        for (int nt = 0; nt < 8; nt++) {
            int row = m0 + wm * 32 + mt * 16 + g;
            int col = n0 + wn * 64 + nt * 8 + 2 * tg;
            float* p0 = C + (size_t)row * N + col;
            float* p1 = C + (size_t)(row + 8) * N + col;
            float v0 = acc[mt][nt][0], v1 = acc[mt][nt][1];
            float v2 = acc[mt][nt][2], v3 = acc[mt][nt][3];
            float2 o0, o1;
            if (EPI == 0) {
                o0 = make_float2(v0, v1); o1 = make_float2(v2, v3);
            } else if (EPI == 1) {
                o0 = make_float2(v0 / (1.f + __expf(-v0)),
                                 v1 / (1.f + __expf(-v1)));
                o1 = make_float2(v2 / (1.f + __expf(-v2)),
                                 v3 / (1.f + __expf(-v3)));
            } else if (EPI == 2) {
                float2 c0 = *(const float2*)p0, c1 = *(const float2*)p1;
                o0 = make_float2(v0 * c0.x, v1 * c0.y);
                o1 = make_float2(v2 * c1.x, v3 * c1.y);
            } else {
                float2 c0 = *(const float2*)p0, c1 = *(const float2*)p1;
                o0 = make_float2(v0 + c0.x, v1 + c0.y);
                o1 = make_float2(v2 + c1.x, v3 + c1.y);
            }
            *(float2*)p0 = o0;
            *(float2*)p1 = o1;
        }
    }
}

// ---------------- RMSNorm ----------------
__global__ __launch_bounds__(256) void rmsnorm_k(const float* __restrict__ x,
                                                 const float* __restrict__ g,
                                                 float* __restrict__ out) {
    int t = blockIdx.x;
    const float* xr = x + (size_t)t * CC;
    float ss = 0.f;
    for (int c = threadIdx.x; c < CC; c += 256) { float v = xr[c]; ss += v * v; }
    __shared__ float red[256];
    red[threadIdx.x] = ss; __syncthreads();
    for (int o = 128; o > 0; o >>= 1) {
        if (threadIdx.x < o) red[threadIdx.x] += red[threadIdx.x + o];
        __syncthreads();
    }
    float r = rsqrtf(red[0] * (1.0f / CC) + 1e-6f);
    float* orow = out + (size_t)t * CC;
    for (int c = threadIdx.x; c < CC; c += 256) orow[c] = xr[c] * r * g[c];
}

// ---------------- sliding-window attention --------------------------------
__global__ __launch_bounds__(256) void attn_k(const float* __restrict__ qkv,
                                              float* __restrict__ out) {
    __shared__ float Qs[64][65];
    __shared__ float Ks[32][65];
    __shared__ float Vs[32][65];
    __shared__ float Ps[64][33];

    int qt = blockIdx.x, h = blockIdx.y, b = blockIdx.z;
    int tid = threadIdx.x;
    int qbase = qt * 64;
    int tokbase = b * TT + qbase;

    for (int i = tid; i < 64 * 64; i += 256) {
        int r = i >> 6, c = i & 63;
        Qs[r][c] = qkv[(size_t)(tokbase + r) * 3072 + h * 64 + c];
    }

    int ty = tid >> 2, tx = tid & 3;
    float O[16];
    #pragma unroll
    for (int j = 0; j < 16; j++) O[j] = 0.f;
    float m = -1e30f, l = 0.f;

    int kt0 = (qbase - (WW - 1)) > 0 ? (qbase - (WW - 1)) >> 5 : 0;
    int kt1 = 2 * qt + 1;
    int q_g = qbase + ty;

    __syncthreads();
    for (int kt = kt0; kt <= kt1; kt++) {
        int kb = kt * 32;
        for (int i = tid; i < 32 * 64; i += 256) {
            int r = i >> 6, c = i & 63;
            size_t base = (size_t)(b * TT + kb + r) * 3072 + h * 64 + c;
            Ks[r][c] = qkv[base + 1024];
            Vs[r][c] = qkv[base + 2048];
        }
        __syncthreads();

        float s[8];
        #pragma unroll
        for (int i = 0; i < 8; i++) s[i] = 0.f;
        for (int d = 0; d < 64; d++) {
            float qv = Qs[ty][d];
            #pragma unroll
            for (int i = 0; i < 8; i++) s[i] += qv * Ks[tx * 8 + i][d];
        }
        float mx = -1e30f;
        #pragma unroll
        for (int i = 0; i < 8; i++) {
            int k_g = kb + tx * 8 + i;
            bool ok = (k_g <= q_g) && (k_g >= q_g - (WW - 1));
            s[i] = ok ? s[i] * 0.125f : -__int_as_float(0x7f800000);
            mx = fmaxf(mx, s[i]);
        }
        mx = fmaxf(mx, __shfl_xor_sync(0xffffffffu, mx, 1));
        mx = fmaxf(mx, __shfl_xor_sync(0xffffffffu, mx, 2));
        float mn = fmaxf(m, mx);
        float alpha = __expf(m - mn);
        m = mn;
        float ls = 0.f;
        #pragma unroll
        for (int i = 0; i < 8; i++) {
            float p = __expf(s[i] - mn);
            Ps[ty][tx * 8 + i] = p;
            ls += p;
        }
        ls += __shfl_xor_sync(0xffffffffu, ls, 1);
        ls += __shfl_xor_sync(0xffffffffu, ls, 2);
        l = l * alpha + ls;
        #pragma unroll
        for (int j = 0; j < 16; j++) O[j] *= alpha;
        __syncwarp();
        for (int kk = 0; kk < 32; kk++) {
            float p = Ps[ty][kk];
            #pragma unroll
            for (int j = 0; j < 16; j++) O[j] += p * Vs[kk][tx * 16 + j];
        }
        __syncthreads();
    }
    float inv = 1.f / l;
    float* orow = out + (size_t)(tokbase + ty) * 1024 + h * 64 + tx * 16;
    #pragma unroll
    for (int j = 0; j < 16; j++) orow[j] = O[j] * inv;
}

// ---------------- gate ----------------
__global__ __launch_bounds__(128) void gate_k(const float* __restrict__ h,
                                              const float* __restrict__ gw,
                                              const float* __restrict__ gb,
                                              float* __restrict__ gates) {
    int t = blockIdx.x;
    const float* hr = h + (size_t)t * CC;
    float s0 = 0.f, s2 = 0.f;
    for (int c = threadIdx.x; c < CC; c += 128) {
        float hv = hr[c];
        s0 += hv * gw[c * 3 + 0];
        s2 += hv * gw[c * 3 + 2];
    }
    __shared__ float r0[128], r2[128];
    r0[threadIdx.x] = s0; r2[threadIdx.x] = s2; __syncthreads();
    for (int o = 64; o > 0; o >>= 1) {
        if (threadIdx.x < o) { r0[threadIdx.x] += r0[threadIdx.x + o];
                               r2[threadIdx.x] += r2[threadIdx.x + o]; }
        __syncthreads();
    }
    if (threadIdx.x == 0) {
        float l0 = r0[0] + gb[0], l2 = r2[0] + gb[2];
        float mx = fmaxf(l0, l2);
        float e0 = __expf(l0 - mx), e2 = __expf(l2 - mx);
        float inv = 1.f / (e0 + e2);
        gates[t * 2 + 0] = e0 * inv;
        gates[t * 2 + 1] = e2 * inv;
    }
}

// ---------------- retrieval projection ----------------
__global__ __launch_bounds__(128) void ret_k(const float* __restrict__ rc,
                                             const float* __restrict__ W,
                                             float* __restrict__ out) {
    int b = blockIdx.y;
    int c = blockIdx.x * 128 + threadIdx.x;
    float acc = 0.f;
    const float* r = rc + (size_t)b * CC;
    for (int k = 0; k < CC; k++) acc += r[k] * W[(size_t)k * CC + c];
    out[(size_t)b * CC + c] = acc;
}

// ---------------- gated mix + residual ----------------
__global__ __launch_bounds__(256) void mix_k(float* __restrict__ x,
                                             const float* __restrict__ ao,
                                             const float* __restrict__ ret,
                                             const float* __restrict__ gates) {
    int idx = blockIdx.x * 256 + threadIdx.x;
    int t = idx >> 10, c = idx & 1023, b = t >> 11;
    x[idx] += gates[t * 2] * ao[idx] + gates[t * 2 + 1] * ret[b * CC + c];
}

// ---------------- launch ----------------------------------------------------
extern "C" void kernel_launch(void* const* d_in, const int* in_sizes, int n_in,
                              void* d_out, int out_size) {
    const float* x_in   = (const float*)d_in[0];
    const float* retc   = (const float*)d_in[1];
    const float* norm1g = (const float*)d_in[2];
    const float* Wqkv   = (const float*)d_in[3];
    const float* Wproj  = (const float*)d_in[4];
    const float* gateW  = (const float*)d_in[5];
    const float* gateB  = (const float*)d_in[6];
    const float* retW   = (const float*)d_in[7];
    const float* norm2g = (const float*)d_in[8];
    const float* WfG    = (const float*)d_in[9];
    const float* WfU    = (const float*)d_in[10];
    const float* WfD    = (const float*)d_in[11];
    float* x = (float*)d_out;

    float *hb, *qkvb, *attb, *projb, *bigb, *retb, *gatesb;
    cudaGetSymbolAddress((void**)&hb,    g_h);
    cudaGetSymbolAddress((void**)&qkvb,  g_qkv);
    cudaGetSymbolAddress((void**)&attb,  g_att);
    cudaGetSymbolAddress((void**)&projb, g_proj);
    cudaGetSymbolAddress((void**)&bigb,  g_big);
    cudaGetSymbolAddress((void**)&retb,  g_ret);
    cudaGetSymbolAddress((void**)&gatesb,g_gates);

    cudaFuncSetAttribute(tgemm_k<0>, cudaFuncAttributeMaxDynamicSharedMemorySize, SMEM_BYTES);
    cudaFuncSetAttribute(tgemm_k<1>, cudaFuncAttributeMaxDynamicSharedMemorySize, SMEM_BYTES);
    cudaFuncSetAttribute(tgemm_k<2>, cudaFuncAttributeMaxDynamicSharedMemorySize, SMEM_BYTES);
    cudaFuncSetAttribute(tgemm_k<3>, cudaFuncAttributeMaxDynamicSharedMemorySize, SMEM_BYTES);

    cudaMemcpyAsync(x, x_in, sizeof(float) * (size_t)NTOK * CC,
                    cudaMemcpyDeviceToDevice, 0);

    for (int l = 0; l < LL; l++) {
        const float* Wqkv_l  = Wqkv  + (size_t)l * CC * 3 * CC;
        const float* Wproj_l = Wproj + (size_t)l * CC * CC;
        const float* gateW_l = gateW + (size_t)l * CC * 3;
        const float* gateB_l = gateB + (size_t)l * 3;
        const float* retW_l  = retW  + (size_t)l * CC * CC;
        const float* WfG_l   = WfG   + (size_t)l * CC * FF;
        const float* WfU_l   = WfU   + (size_t)l * CC * FF;
        const float* WfD_l   = WfD   + (size_t)l * FF * CC;

        rmsnorm_k<<<NTOK, 256>>>(x, norm1g + l * CC, hb);
        tgemm_k<0><<<dim3(3 * CC / 128, NTOK / 128), 256, SMEM_BYTES>>>(
            hb, Wqkv_l, qkvb, NTOK, 3 * CC, CC);
        attn_k<<<dim3(TT / 64, HH, BB), 256>>>(qkvb, attb);
        tgemm_k<0><<<dim3(CC / 128, NTOK / 128), 256, SMEM_BYTES>>>(
            attb, Wproj_l, projb, NTOK, CC, CC);
        gate_k<<<NTOK, 128>>>(hb, gateW_l, gateB_l, gatesb);
        ret_k<<<dim3(CC / 128, BB), 128>>>(retc, retW_l, retb);
        mix_k<<<NTOK * CC / 256, 256>>>(x, projb, retb, gatesb);

        rmsnorm_k<<<NTOK, 256>>>(x, norm2g + l * CC, hb);
        tgemm_k<1><<<dim3(FF / 128, NTOK / 128), 256, SMEM_BYTES>>>(
            hb, WfG_l, bigb, NTOK, FF, CC);
        tgemm_k<2><<<dim3(FF / 128, NTOK / 128), 256, SMEM_BYTES>>>(
            hb, WfU_l, bigb, NTOK, FF, CC);
        tgemm_k<3><<<dim3(CC / 128, NTOK / 128), 256, SMEM_BYTES>>>(
            bigb, WfD_l, x, NTOK, CC, FF);
    }
}